// round 3
// baseline (speedup 1.0000x reference)
#include <cuda_runtime.h>

#define NN 30
#define EPG 240
#define NEDGE 245760
#define ETOT  276480

__device__ float g_h [30720*256];
__device__ float g_y0[30720*256];
__device__ float g_y1[30720*512];
__device__ float g_y2[30720*256];
__device__ float g_z1[1024*512];
__device__ float g_z2[1024*256];
__device__ float g_wlt[64*256];
__device__ float g_wrt[64*256];
__device__ float g_w0t[768*256];
__device__ float g_w1t[768*512];
__device__ float g_ds1t[256*512];
__device__ float g_w2t[1536*256];
__device__ float g_ds2t[512*256];
__device__ float g_fc1p[512*7680];

__device__ __forceinline__ unsigned ford(float f){
    unsigned u = __float_as_uint(f);
    return (u & 0x80000000u) ? ~u : (u | 0x80000000u);
}
__device__ __forceinline__ float finv(unsigned u){
    return __uint_as_float((u & 0x80000000u) ? (u & 0x7fffffffu) : ~u);
}

// ---- weight prep ----
__global__ void k_tr_wlr(const float* __restrict__ wl, const float* __restrict__ wr){
    int i = blockIdx.x*256 + threadIdx.x;
    if (i < 64*256){ int c = i>>6, k = i&63; g_wlt[k*256+c] = wl[i]; g_wrt[k*256+c] = wr[i]; }
}
__global__ void k_tr_w0(const float* __restrict__ w){
    int i = blockIdx.x*256 + threadIdx.x;
    if (i < 256*768){ int co = i/768, r = i - co*768; g_w0t[r*256+co] = w[i]; }
}
__global__ void k_tr_w1(const float* __restrict__ w){
    int i = blockIdx.x*256 + threadIdx.x;
    if (i < 512*768){ int co = i/768, r = i - co*768; g_w1t[r*512+co] = w[i]; }
}
__global__ void k_tr_ds1(const float* __restrict__ w){
    int i = blockIdx.x*256 + threadIdx.x;
    if (i < 512*256){ int co = i>>8, ci = i&255; g_ds1t[ci*512+co] = w[i]; }
}
__global__ void k_tr_w2(const float* __restrict__ w){
    int i = blockIdx.x*256 + threadIdx.x;
    if (i < 256*1536){ int co = i/1536, r = i - co*1536; g_w2t[r*256+co] = w[i]; }
}
__global__ void k_tr_ds2(const float* __restrict__ w){
    int i = blockIdx.x*256 + threadIdx.x;
    if (i < 256*512){ int co = i>>9, ci = i&511; g_ds2t[ci*256+co] = w[i]; }
}
__global__ void k_tr_fc1(const float* __restrict__ w){
    int i = blockIdx.x*256 + threadIdx.x;
    if (i < 512*7680){
        int o = i/7680, kp = i - o*7680;
        int l = kp>>8, c = kp&255;
        g_fc1p[i] = w[o*7680 + c*30 + l];
    }
}
__global__ void k_ei(const int* __restrict__ eidx, float* __restrict__ eo){
    int e = blockIdx.x*256 + threadIdx.x;
    if (e < ETOT){
        float s, d;
        if (e < NEDGE){ s = (float)eidx[e]; d = (float)eidx[NEDGE+e]; }
        else          { s = d = (float)(e - NEDGE); }
        eo[e] = s; eo[ETOT + e] = d;
    }
}

// ---- GATv2 per graph ----
__global__ __launch_bounds__(256) void k_gat(
    const float* __restrict__ x, const float* __restrict__ bl, const float* __restrict__ br,
    const float* __restrict__ att, const float* __restrict__ bias,
    const int* __restrict__ eidx, float* __restrict__ alphaOut)
{
    extern __shared__ float sm[];
    float*    xs    = sm;            // 1920
    float*    xl    = xs + 1920;     // 7680
    float*    xr    = xl + 7680;     // 7680
    float*    atts  = xr + 7680;     // 256
    float*    ea    = atts + 256;    // 1088
    float*    esum  = ea + 1088;     // 120
    unsigned* emaxu = (unsigned*)(esum + 120);  // 120
    int*      srcs  = (int*)(emaxu + 120);      // 272
    int*      dsts  = srcs + 272;               // 272
    int*      cnt   = dsts + 272;               // 32
    int*      lists = cnt + 32;                 // 30*48

    const int b = blockIdx.x, tid = threadIdx.x;

    {
        const float4* s4 = (const float4*)(x + (size_t)b*NN*64);
        float4* d4 = (float4*)xs;
        for (int i = tid; i < 480; i += 256) d4[i] = s4[i];
    }
    atts[tid] = att[tid];
    for (int i = tid; i < 120; i += 256){ emaxu[i] = 0u; esum[i] = 0.f; }
    if (tid < 30) cnt[tid] = 0;
    for (int j = tid; j < 270; j += 256){
        int s, d;
        if (j < EPG){
            s = eidx[(size_t)b*EPG + j] - b*NN;
            d = eidx[NEDGE + (size_t)b*EPG + j] - b*NN;
        } else { s = d = j - EPG; }
        srcs[j] = s; dsts[j] = d;
    }
    __syncthreads();

    {   // xl / xr
        const int c = tid;
        float accl[NN], accr[NN];
        float blv = bl[c], brv = br[c];
        #pragma unroll
        for (int n = 0; n < NN; n++){ accl[n] = blv; accr[n] = brv; }
        for (int k0 = 0; k0 < 64; k0 += 8){
            float wlv[8], wrv[8];
            #pragma unroll
            for (int kk = 0; kk < 8; kk++){
                wlv[kk] = g_wlt[(k0+kk)*256 + c];
                wrv[kk] = g_wrt[(k0+kk)*256 + c];
            }
            #pragma unroll
            for (int n = 0; n < NN; n++){
                #pragma unroll
                for (int kk = 0; kk < 8; kk++){
                    float xv = xs[n*64 + k0 + kk];
                    accl[n] += xv * wlv[kk];
                    accr[n] += xv * wrv[kk];
                }
            }
        }
        #pragma unroll
        for (int n = 0; n < NN; n++){ xl[n*256+c] = accl[n]; xr[n*256+c] = accr[n]; }
    }
    __syncthreads();

    {   // edge scores
        const int warp = tid >> 5, lane = tid & 31;
        const int h4 = lane >> 3, chb = lane * 8;
        for (int e = warp; e < 270; e += 8){
            const float* pl = &xl[srcs[e]*256 + chb];
            const float* pr = &xr[dsts[e]*256 + chb];
            float p = 0.f;
            #pragma unroll
            for (int i = 0; i < 8; i++){
                float v = pl[i] + pr[i];
                v = v > 0.f ? v : 0.2f*v;
                p += v * atts[chb + i];
            }
            p += __shfl_down_sync(0xffffffffu, p, 4, 8);
            p += __shfl_down_sync(0xffffffffu, p, 2, 8);
            p += __shfl_down_sync(0xffffffffu, p, 1, 8);
            if ((lane & 7) == 0) ea[e*4 + h4] = p;
        }
    }
    __syncthreads();

    for (int it = tid; it < 1080; it += 256){
        int e = it >> 2, h = it & 3;
        atomicMax(&emaxu[dsts[e]*4 + h], ford(ea[it]));
    }
    __syncthreads();
    for (int it = tid; it < 1080; it += 256){
        int e = it >> 2, h = it & 3; int d = dsts[e];
        float ex = __expf(ea[it] - finv(emaxu[d*4 + h]));
        ea[it] = ex;
        atomicAdd(&esum[d*4 + h], ex);
    }
    __syncthreads();
    for (int it = tid; it < 1080; it += 256){
        int e = it >> 2, h = it & 3;
        float a = ea[it] / esum[dsts[e]*4 + h];
        ea[it] = a;
        if (alphaOut){
            int grow = (e < EPG) ? (b*EPG + e) : (NEDGE + b*NN + (e - EPG));
            alphaOut[(size_t)grow*4 + h] = a;
        }
    }
    for (int e = tid; e < 270; e += 256){
        int d = dsts[e];
        int slot = atomicAdd(&cnt[d], 1);
        if (slot < 48) lists[d*48 + slot] = e;
    }
    __syncthreads();

    {   // aggregate
        const int c = tid, hh = c >> 6;
        float bv = bias[c];
        for (int n = 0; n < NN; n++){
            float a = 0.f;
            int deg = cnt[n]; if (deg > 48) deg = 48;
            for (int i = 0; i < deg; i++){
                int e = lists[n*48 + i];
                a += ea[e*4 + hh] * xl[srcs[e]*256 + c];
            }
            float v = a + bv;
            g_h[((size_t)(b*NN + n))*256 + c] = v > 0.f ? v : 0.f;
        }
    }
}

// ---- TCN block 0 ----
__global__ __launch_bounds__(256) void k_tcn0(const float* __restrict__ b0,
    const float* __restrict__ lnw, const float* __restrict__ lnb)
{
    __shared__ float hsp[38*256];
    const int b = blockIdx.x, tid = threadIdx.x;
    for (int i = tid; i < 4*256; i += 256){ hsp[i] = 0.f; hsp[34*256 + i] = 0.f; }
    const float* src = g_h + (size_t)b*NN*256;
    for (int i = tid; i < NN*256; i += 256) hsp[4*256 + i] = src[i];
    __syncthreads();
    const int c = tid;
    float acc[NN];
    float bb = b0[c];
    #pragma unroll
    for (int l = 0; l < NN; l++) acc[l] = bb;
    for (int ci = 0; ci < 256; ci++){
        float w0 = g_w0t[(ci*3+0)*256 + c];
        float w1 = g_w0t[(ci*3+1)*256 + c];
        float w2 = g_w0t[(ci*3+2)*256 + c];
        float hv[32];
        #pragma unroll
        for (int i = 0; i < 32; i++) hv[i] = hsp[(3+i)*256 + ci];
        #pragma unroll
        for (int l = 0; l < NN; l++)
            acc[l] += hv[l]*w0 + hv[l+1]*w1 + hv[l+2]*w2;
    }
    float mu = 0.f;
    #pragma unroll
    for (int l = 0; l < NN; l++) mu += acc[l];
    mu *= (1.f/NN);
    float s2 = 0.f;
    #pragma unroll
    for (int l = 0; l < NN; l++){ float d = acc[l]-mu; s2 += d*d; }
    float rs = rsqrtf(s2*(1.f/NN) + 1e-5f);
    float* dst = g_y0 + (size_t)b*NN*256;
    #pragma unroll
    for (int l = 0; l < NN; l++){
        float v = (acc[l]-mu)*rs*__ldg(&lnw[l]) + __ldg(&lnb[l]);
        v = v > 0.f ? v : 0.f;
        dst[l*256 + c] = v + hsp[(4+l)*256 + c];
    }
}

// ---- TCN block 1 ----
__global__ __launch_bounds__(512) void k_tcn1(const float* __restrict__ b1, const float* __restrict__ dsb,
    const float* __restrict__ lnw, const float* __restrict__ lnb)
{
    __shared__ float hsp[38*256];
    const int b = blockIdx.x, tid = threadIdx.x;
    for (int i = tid; i < 4*256; i += 512){ hsp[i] = 0.f; hsp[34*256 + i] = 0.f; }
    const float* src = g_y0 + (size_t)b*NN*256;
    for (int i = tid; i < NN*256; i += 512) hsp[4*256 + i] = src[i];
    __syncthreads();
    const int co = tid;
    float acc[NN], accd[NN];
    float bb = b1[co], bd = dsb[co];
    #pragma unroll
    for (int l = 0; l < NN; l++){ acc[l] = bb; accd[l] = bd; }
    for (int ci = 0; ci < 256; ci++){
        float w0 = g_w1t[(ci*3+0)*512 + co];
        float w1 = g_w1t[(ci*3+1)*512 + co];
        float w2 = g_w1t[(ci*3+2)*512 + co];
        float wd = g_ds1t[ci*512 + co];
        float hv[34];
        #pragma unroll
        for (int i = 0; i < 34; i++) hv[i] = hsp[(2+i)*256 + ci];
        #pragma unroll
        for (int l = 0; l < NN; l++){
            acc[l]  += hv[l]*w0 + hv[l+2]*w1 + hv[l+4]*w2;
            accd[l] += hv[l+2]*wd;
        }
    }
    float mu = 0.f;
    #pragma unroll
    for (int l = 0; l < NN; l++) mu += acc[l];
    mu *= (1.f/NN);
    float s2 = 0.f;
    #pragma unroll
    for (int l = 0; l < NN; l++){ float d = acc[l]-mu; s2 += d*d; }
    float rs = rsqrtf(s2*(1.f/NN) + 1e-5f);
    float* dst = g_y1 + (size_t)b*NN*512;
    #pragma unroll
    for (int l = 0; l < NN; l++){
        float v = (acc[l]-mu)*rs*__ldg(&lnw[l]) + __ldg(&lnb[l]);
        v = v > 0.f ? v : 0.f;
        dst[l*512 + co] = v + accd[l];
    }
}

// ---- TCN block 2 ----
__global__ __launch_bounds__(256) void k_tcn2(const float* __restrict__ b2, const float* __restrict__ dsb,
    const float* __restrict__ lnw, const float* __restrict__ lnb)
{
    extern __shared__ float hsp2[];   // 38*512 floats
    const int b = blockIdx.x, tid = threadIdx.x;
    for (int i = tid; i < 4*512; i += 256){ hsp2[i] = 0.f; hsp2[34*512 + i] = 0.f; }
    const float* src = g_y1 + (size_t)b*NN*512;
    for (int i = tid; i < NN*512; i += 256) hsp2[4*512 + i] = src[i];
    __syncthreads();
    const int co = tid;
    float acc[NN], accd[NN];
    float bb = b2[co], bd = dsb[co];
    #pragma unroll
    for (int l = 0; l < NN; l++){ acc[l] = bb; accd[l] = bd; }
    for (int ci = 0; ci < 512; ci++){
        float w0 = g_w2t[(ci*3+0)*256 + co];
        float w1 = g_w2t[(ci*3+1)*256 + co];
        float w2 = g_w2t[(ci*3+2)*256 + co];
        float wd = g_ds2t[ci*256 + co];
        float hv[38];
        #pragma unroll
        for (int i = 0; i < 38; i++) hv[i] = hsp2[i*512 + ci];
        #pragma unroll
        for (int l = 0; l < NN; l++){
            acc[l]  += hv[l]*w0 + hv[l+4]*w1 + hv[l+8]*w2;
            accd[l] += hv[l+4]*wd;
        }
    }
    float mu = 0.f;
    #pragma unroll
    for (int l = 0; l < NN; l++) mu += acc[l];
    mu *= (1.f/NN);
    float s2 = 0.f;
    #pragma unroll
    for (int l = 0; l < NN; l++){ float d = acc[l]-mu; s2 += d*d; }
    float rs = rsqrtf(s2*(1.f/NN) + 1e-5f);
    float* dst = g_y2 + (size_t)b*NN*256;
    #pragma unroll
    for (int l = 0; l < NN; l++){
        float v = (acc[l]-mu)*rs*__ldg(&lnw[l]) + __ldg(&lnb[l]);
        v = v > 0.f ? v : 0.f;
        dst[l*256 + co] = v + accd[l];
    }
}

// ---- tiled GEMM body: C[M,N] = act(A[M,K] @ Bw[N,K]^T + bias) ----
__device__ __forceinline__ void gemm_body(const float* __restrict__ A, const float* __restrict__ Bw,
    const float* __restrict__ bias, float* __restrict__ C, int M, int N, int K, bool doRelu)
{
    __shared__ __align__(16) float As2[16][68];
    __shared__ __align__(16) float Bs2[16][68];
    const int tid = threadIdx.x;
    const int tx = tid & 15, ty = tid >> 4;
    const int m0 = blockIdx.y*64, n0 = blockIdx.x*64;
    const int lm = tid >> 2, lk = (tid & 3)*4;
    float acc[4][4];
    #pragma unroll
    for (int i = 0; i < 4; i++)
        #pragma unroll
        for (int j = 0; j < 4; j++) acc[i][j] = 0.f;

    for (int k0 = 0; k0 < K; k0 += 16){
        float4 av = *(const float4*)&A[(size_t)(m0+lm)*K + k0 + lk];
        float4 bv = make_float4(0.f,0.f,0.f,0.f);
        if (n0 + lm < N) bv = *(const float4*)&Bw[(size_t)(n0+lm)*K + k0 + lk];
        As2[lk+0][lm] = av.x; As2[lk+1][lm] = av.y; As2[lk+2][lm] = av.z; As2[lk+3][lm] = av.w;
        Bs2[lk+0][lm] = bv.x; Bs2[lk+1][lm] = bv.y; Bs2[lk+2][lm] = bv.z; Bs2[lk+3][lm] = bv.w;
        __syncthreads();
        #pragma unroll
        for (int k = 0; k < 16; k++){
            float4 a  = *(const float4*)&As2[k][ty*4];
            float4 bb = *(const float4*)&Bs2[k][tx*4];
            acc[0][0] += a.x*bb.x; acc[0][1] += a.x*bb.y; acc[0][2] += a.x*bb.z; acc[0][3] += a.x*bb.w;
            acc[1][0] += a.y*bb.x; acc[1][1] += a.y*bb.y; acc[1][2] += a.y*bb.z; acc[1][3] += a.y*bb.w;
            acc[2][0] += a.z*bb.x; acc[2][1] += a.z*bb.y; acc[2][2] += a.z*bb.z; acc[2][3] += a.z*bb.w;
            acc[3][0] += a.w*bb.x; acc[3][1] += a.w*bb.y; acc[3][2] += a.w*bb.z; acc[3][3] += a.w*bb.w;
        }
        __syncthreads();
    }
    #pragma unroll
    for (int i = 0; i < 4; i++){
        int row = m0 + ty*4 + i;
        #pragma unroll
        for (int j = 0; j < 4; j++){
            int col = n0 + tx*4 + j;
            if (col < N){
                float v = acc[i][j] + __ldg(&bias[col]);
                if (doRelu) v = v > 0.f ? v : 0.f;
                C[(size_t)row*N + col] = v;
            }
        }
    }
}
// wrappers referencing device globals FROM DEVICE CODE (host cannot pass their addresses)
__global__ __launch_bounds__(256) void k_fc1(const float* __restrict__ bias){
    gemm_body(g_y2, g_fc1p, bias, g_z1, 1024, 512, 7680, true);
}
__global__ __launch_bounds__(256) void k_fc2(const float* __restrict__ w, const float* __restrict__ bias){
    gemm_body(g_z1, w, bias, g_z2, 1024, 256, 512, true);
}
__global__ __launch_bounds__(256) void k_fc3(const float* __restrict__ w, const float* __restrict__ bias,
                                             float* __restrict__ out){
    gemm_body(g_z2, w, bias, out, 1024, 144, 256, false);
}

extern "C" void kernel_launch(void* const* d_in, const int* in_sizes, int n_in,
                              void* d_out, int out_size) {
    const float* x      = (const float*)d_in[0];
    const float* gWl    = (const float*)d_in[1];
    const float* gbl    = (const float*)d_in[2];
    const float* gWr    = (const float*)d_in[3];
    const float* gbr    = (const float*)d_in[4];
    const float* gatt   = (const float*)d_in[5];
    const float* gbias  = (const float*)d_in[6];
    const float* t0w    = (const float*)d_in[7];
    const float* t0b    = (const float*)d_in[8];
    const float* ln0w   = (const float*)d_in[9];
    const float* ln0b   = (const float*)d_in[10];
    const float* t1w    = (const float*)d_in[11];
    const float* t1b    = (const float*)d_in[12];
    const float* ln1w   = (const float*)d_in[13];
    const float* ln1b   = (const float*)d_in[14];
    const float* ds1w   = (const float*)d_in[15];
    const float* ds1b   = (const float*)d_in[16];
    const float* t2w    = (const float*)d_in[17];
    const float* t2b    = (const float*)d_in[18];
    const float* ln2w   = (const float*)d_in[19];
    const float* ln2b   = (const float*)d_in[20];
    const float* ds2w   = (const float*)d_in[21];
    const float* ds2b   = (const float*)d_in[22];
    const float* fc1b   = (const float*)d_in[24];
    const float* fc2w   = (const float*)d_in[25];
    const float* fc2b   = (const float*)d_in[26];
    const float* fc3w   = (const float*)d_in[27];
    const float* fc3b   = (const float*)d_in[28];
    const float* fc1w   = (const float*)d_in[23];
    const int*   eidx   = (const int*)d_in[29];

    float* outp = (float*)d_out;
    bool full = (out_size >= 147456 + ETOT*4 + 2*ETOT);
    float* alphaOut = full ? (outp + 147456) : nullptr;
    float* eiOut    = full ? (outp + 147456 + ETOT*4) : nullptr;

    cudaFuncSetAttribute(k_gat,  cudaFuncAttributeMaxDynamicSharedMemorySize, 84*1024);
    cudaFuncSetAttribute(k_tcn2, cudaFuncAttributeMaxDynamicSharedMemorySize, 38*512*4);

    // weight prep
    k_tr_wlr<<<64,256>>>(gWl, gWr);
    k_tr_w0 <<<768,256>>>(t0w);
    k_tr_w1 <<<1536,256>>>(t1w);
    k_tr_ds1<<<512,256>>>(ds1w);
    k_tr_w2 <<<1536,256>>>(t2w);
    k_tr_ds2<<<512,256>>>(ds2w);
    k_tr_fc1<<<15360,256>>>(fc1w);
    if (eiOut) k_ei<<<1080,256>>>(eidx, eiOut);

    k_gat<<<1024,256, 84*1024>>>(x, gbl, gbr, gatt, gbias, eidx, alphaOut);
    k_tcn0<<<1024,256>>>(t0b, ln0w, ln0b);
    k_tcn1<<<1024,512>>>(t1b, ds1b, ln1w, ln1b);
    k_tcn2<<<1024,256, 38*512*4>>>(t2b, ds2b, ln2w, ln2b);

    dim3 g1(8,16);  k_fc1<<<g1,256>>>(fc1b);
    dim3 g2(4,16);  k_fc2<<<g2,256>>>(fc2w, fc2b);
    dim3 g3(3,16);  k_fc3<<<g3,256>>>(fc3w, fc3b, outp);
}

// round 5
// speedup vs baseline: 1.9337x; 1.9337x over previous
#include <cuda_runtime.h>

#define NN 30
#define EPG 240
#define NEDGE 245760
#define ETOT  276480

typedef unsigned long long u64;

__device__ float g_h [30720*256];
__device__ float g_y0[30720*256];
__device__ float g_y1[30720*512];
__device__ float g_y2[30720*256];
__device__ float g_z1[1024*512];
__device__ float g_z2[1024*256];
__device__ float g_wlt[64*256];
__device__ float g_wrt[64*256];
__device__ float g_w0t[768*256];
__device__ float g_w1t[768*512];
__device__ float g_ds1t[256*512];
__device__ float g_w2t[1536*256];
__device__ float g_ds2t[512*256];
__device__ float g_fc1p[512*7680];

__device__ __forceinline__ unsigned ford(float f){
    unsigned u = __float_as_uint(f);
    return (u & 0x80000000u) ? ~u : (u | 0x80000000u);
}
__device__ __forceinline__ float finv(unsigned u){
    return __uint_as_float((u & 0x80000000u) ? (u & 0x7fffffffu) : ~u);
}

// ---- f32x2 helpers ----
__device__ __forceinline__ u64 dup2(float v){
    u64 r; asm("mov.b64 %0, {%1, %1};" : "=l"(r) : "f"(v)); return r;
}
__device__ __forceinline__ u64 pk2(float x, float y){
    u64 r; asm("mov.b64 %0, {%1, %2};" : "=l"(r) : "f"(x), "f"(y)); return r;
}
__device__ __forceinline__ float2 unp2(u64 v){
    float2 r; asm("mov.b64 {%0, %1}, %2;" : "=f"(r.x), "=f"(r.y) : "l"(v)); return r;
}
__device__ __forceinline__ void fma2(u64& a, u64 b, u64 c){
    asm("fma.rn.f32x2 %0, %1, %2, %0;" : "+l"(a) : "l"(b), "l"(c));
}

// ---- weight prep ----
__global__ void k_tr_wlr(const float* __restrict__ wl, const float* __restrict__ wr){
    int i = blockIdx.x*256 + threadIdx.x;
    if (i < 64*256){ int c = i>>6, k = i&63; g_wlt[k*256+c] = wl[i]; g_wrt[k*256+c] = wr[i]; }
}
__global__ void k_tr_w0(const float* __restrict__ w){
    int i = blockIdx.x*256 + threadIdx.x;
    if (i < 256*768){ int co = i/768, r = i - co*768; g_w0t[r*256+co] = w[i]; }
}
__global__ void k_tr_w1(const float* __restrict__ w){
    int i = blockIdx.x*256 + threadIdx.x;
    if (i < 512*768){ int co = i/768, r = i - co*768; g_w1t[r*512+co] = w[i]; }
}
__global__ void k_tr_ds1(const float* __restrict__ w){
    int i = blockIdx.x*256 + threadIdx.x;
    if (i < 512*256){ int co = i>>8, ci = i&255; g_ds1t[ci*512+co] = w[i]; }
}
__global__ void k_tr_w2(const float* __restrict__ w){
    int i = blockIdx.x*256 + threadIdx.x;
    if (i < 256*1536){ int co = i/1536, r = i - co*1536; g_w2t[r*256+co] = w[i]; }
}
__global__ void k_tr_ds2(const float* __restrict__ w){
    int i = blockIdx.x*256 + threadIdx.x;
    if (i < 256*512){ int co = i>>9, ci = i&511; g_ds2t[ci*256+co] = w[i]; }
}
__global__ void k_tr_fc1(const float* __restrict__ w){
    int i = blockIdx.x*256 + threadIdx.x;
    if (i < 512*7680){
        int o = i/7680, kp = i - o*7680;
        int l = kp>>8, c = kp&255;
        g_fc1p[i] = w[o*7680 + c*30 + l];
    }
}
__global__ void k_ei(const int* __restrict__ eidx, float* __restrict__ eo){
    int e = blockIdx.x*256 + threadIdx.x;
    if (e < ETOT){
        float s, d;
        if (e < NEDGE){ s = (float)eidx[e]; d = (float)eidx[NEDGE+e]; }
        else          { s = d = (float)(e - NEDGE); }
        eo[e] = s; eo[ETOT + e] = d;
    }
}

// ---- GATv2 per graph ----
__global__ __launch_bounds__(256) void k_gat(
    const float* __restrict__ x, const float* __restrict__ bl, const float* __restrict__ br,
    const float* __restrict__ att, const float* __restrict__ bias,
    const int* __restrict__ eidx, float* __restrict__ alphaOut)
{
    extern __shared__ float sm[];
    float*    xs    = sm;
    float*    xl    = xs + 1920;
    float*    xr    = xl + 7680;
    float*    atts  = xr + 7680;
    float*    ea    = atts + 256;
    float*    esum  = ea + 1088;
    unsigned* emaxu = (unsigned*)(esum + 120);
    int*      srcs  = (int*)(emaxu + 120);
    int*      dsts  = srcs + 272;
    int*      cnt   = dsts + 272;
    int*      lists = cnt + 32;

    const int b = blockIdx.x, tid = threadIdx.x;

    {
        const float4* s4 = (const float4*)(x + (size_t)b*NN*64);
        float4* d4 = (float4*)xs;
        for (int i = tid; i < 480; i += 256) d4[i] = s4[i];
    }
    atts[tid] = att[tid];
    for (int i = tid; i < 120; i += 256){ emaxu[i] = 0u; esum[i] = 0.f; }
    if (tid < 30) cnt[tid] = 0;
    for (int j = tid; j < 270; j += 256){
        int s, d;
        if (j < EPG){
            s = eidx[(size_t)b*EPG + j] - b*NN;
            d = eidx[NEDGE + (size_t)b*EPG + j] - b*NN;
        } else { s = d = j - EPG; }
        srcs[j] = s; dsts[j] = d;
    }
    __syncthreads();

    {
        const int c = tid;
        float accl[NN], accr[NN];
        float blv = bl[c], brv = br[c];
        #pragma unroll
        for (int n = 0; n < NN; n++){ accl[n] = blv; accr[n] = brv; }
        for (int k0 = 0; k0 < 64; k0 += 8){
            float wlv[8], wrv[8];
            #pragma unroll
            for (int kk = 0; kk < 8; kk++){
                wlv[kk] = g_wlt[(k0+kk)*256 + c];
                wrv[kk] = g_wrt[(k0+kk)*256 + c];
            }
            #pragma unroll
            for (int n = 0; n < NN; n++){
                #pragma unroll
                for (int kk = 0; kk < 8; kk++){
                    float xv = xs[n*64 + k0 + kk];
                    accl[n] += xv * wlv[kk];
                    accr[n] += xv * wrv[kk];
                }
            }
        }
        #pragma unroll
        for (int n = 0; n < NN; n++){ xl[n*256+c] = accl[n]; xr[n*256+c] = accr[n]; }
    }
    __syncthreads();

    {
        const int warp = tid >> 5, lane = tid & 31;
        const int h4 = lane >> 3, chb = lane * 8;
        for (int e = warp; e < 270; e += 8){
            const float* pl = &xl[srcs[e]*256 + chb];
            const float* pr = &xr[dsts[e]*256 + chb];
            float p = 0.f;
            #pragma unroll
            for (int i = 0; i < 8; i++){
                float v = pl[i] + pr[i];
                v = v > 0.f ? v : 0.2f*v;
                p += v * atts[chb + i];
            }
            p += __shfl_down_sync(0xffffffffu, p, 4, 8);
            p += __shfl_down_sync(0xffffffffu, p, 2, 8);
            p += __shfl_down_sync(0xffffffffu, p, 1, 8);
            if ((lane & 7) == 0) ea[e*4 + h4] = p;
        }
    }
    __syncthreads();

    for (int it = tid; it < 1080; it += 256){
        int e = it >> 2, h = it & 3;
        atomicMax(&emaxu[dsts[e]*4 + h], ford(ea[it]));
    }
    __syncthreads();
    for (int it = tid; it < 1080; it += 256){
        int e = it >> 2, h = it & 3; int d = dsts[e];
        float ex = __expf(ea[it] - finv(emaxu[d*4 + h]));
        ea[it] = ex;
        atomicAdd(&esum[d*4 + h], ex);
    }
    __syncthreads();
    for (int it = tid; it < 1080; it += 256){
        int e = it >> 2, h = it & 3;
        float a = ea[it] / esum[dsts[e]*4 + h];
        ea[it] = a;
        if (alphaOut){
            int grow = (e < EPG) ? (b*EPG + e) : (NEDGE + b*NN + (e - EPG));
            alphaOut[(size_t)grow*4 + h] = a;
        }
    }
    for (int e = tid; e < 270; e += 256){
        int d = dsts[e];
        int slot = atomicAdd(&cnt[d], 1);
        if (slot < 48) lists[d*48 + slot] = e;
    }
    __syncthreads();

    {
        const int c = tid, hh = c >> 6;
        float bv = bias[c];
        for (int n = 0; n < NN; n++){
            float a = 0.f;
            int deg = cnt[n]; if (deg > 48) deg = 48;
            for (int i = 0; i < deg; i++){
                int e = lists[n*48 + i];
                a += ea[e*4 + hh] * xl[srcs[e]*256 + c];
            }
            float v = a + bv;
            g_h[((size_t)(b*NN + n))*256 + c] = v > 0.f ? v : 0.f;
        }
    }
}

// ---- TCN block 0: 256->256, dil 1, identity residual. smem transposed [ci][34] ----
__global__ __launch_bounds__(256) void k_tcn0(const float* __restrict__ b0,
    const float* __restrict__ lnw, const float* __restrict__ lnb)
{
    __shared__ __align__(16) float hsp[256*34];
    const int b = blockIdx.x, tid = threadIdx.x;
    for (int i = tid; i < 256*34; i += 256) hsp[i] = 0.f;
    __syncthreads();
    const float* src = g_h + (size_t)b*NN*256;
    for (int idx = tid; idx < NN*256; idx += 256){
        int l = idx >> 8, c = idx & 255;
        hsp[c*34 + l + 1] = src[idx];
    }
    __syncthreads();
    const int c = tid;
    u64 acc2[15];
    {
        u64 bb = dup2(b0[c]);
        #pragma unroll
        for (int j = 0; j < 15; j++) acc2[j] = bb;
    }
    for (int ci = 0; ci < 256; ci++){
        const float* row = &hsp[ci*34];
        u64 w0d = dup2(g_w0t[(ci*3+0)*256 + c]);
        u64 w1d = dup2(g_w0t[(ci*3+1)*256 + c]);
        u64 w2d = dup2(g_w0t[(ci*3+2)*256 + c]);
        u64 E0 = *(const u64*)(row);
        #pragma unroll
        for (int j = 0; j < 15; j++){
            u64 E1 = *(const u64*)(row + 2*j + 2);
            float2 e0 = unp2(E0), e1 = unp2(E1);
            u64 O = pk2(e0.y, e1.x);
            fma2(acc2[j], w0d, E0);
            fma2(acc2[j], w1d, O);
            fma2(acc2[j], w2d, E1);
            E0 = E1;
        }
    }
    float a[NN];
    #pragma unroll
    for (int j = 0; j < 15; j++){ float2 t = unp2(acc2[j]); a[2*j] = t.x; a[2*j+1] = t.y; }
    float mu = 0.f;
    #pragma unroll
    for (int l = 0; l < NN; l++) mu += a[l];
    mu *= (1.f/NN);
    float s2 = 0.f;
    #pragma unroll
    for (int l = 0; l < NN; l++){ float d = a[l]-mu; s2 += d*d; }
    float rs = rsqrtf(s2*(1.f/NN) + 1e-5f);
    float* dst = g_y0 + (size_t)b*NN*256;
    #pragma unroll
    for (int l = 0; l < NN; l++){
        float v = (a[l]-mu)*rs*__ldg(&lnw[l]) + __ldg(&lnb[l]);
        v = v > 0.f ? v : 0.f;
        dst[l*256 + c] = v + hsp[c*34 + l + 1];
    }
}

// ---- TCN block 1: 256->512, dil 2, 1x1 downsample. smem transposed [ci][38] ----
__global__ __launch_bounds__(512) void k_tcn1(const float* __restrict__ b1, const float* __restrict__ dsb,
    const float* __restrict__ lnw, const float* __restrict__ lnb)
{
    __shared__ __align__(16) float hsp[256*38];
    const int b = blockIdx.x, tid = threadIdx.x;
    for (int i = tid; i < 256*38; i += 512) hsp[i] = 0.f;
    __syncthreads();
    const float* src = g_y0 + (size_t)b*NN*256;
    for (int idx = tid; idx < NN*256; idx += 512){
        int l = idx >> 8, c = idx & 255;
        hsp[c*38 + l + 2] = src[idx];
    }
    __syncthreads();
    const int co = tid;
    u64 acc2[15], accd2[15];
    {
        u64 bb = dup2(b1[co]), bd = dup2(dsb[co]);
        #pragma unroll
        for (int j = 0; j < 15; j++){ acc2[j] = bb; accd2[j] = bd; }
    }
    for (int ci = 0; ci < 256; ci++){
        const float* row = &hsp[ci*38];
        u64 w0d = dup2(g_w1t[(ci*3+0)*512 + co]);
        u64 w1d = dup2(g_w1t[(ci*3+1)*512 + co]);
        u64 w2d = dup2(g_w1t[(ci*3+2)*512 + co]);
        u64 wdd = dup2(g_ds1t[ci*512 + co]);
        u64 E0 = *(const u64*)(row);
        u64 E1 = *(const u64*)(row + 2);
        #pragma unroll
        for (int j = 0; j < 15; j++){
            u64 E2 = *(const u64*)(row + 2*j + 4);
            fma2(acc2[j], w0d, E0);
            fma2(acc2[j], w1d, E1);
            fma2(acc2[j], w2d, E2);
            fma2(accd2[j], wdd, E1);
            E0 = E1; E1 = E2;
        }
    }
    float a[NN], dd[NN];
    #pragma unroll
    for (int j = 0; j < 15; j++){
        float2 t = unp2(acc2[j]);  a[2*j] = t.x;  a[2*j+1] = t.y;
        float2 u = unp2(accd2[j]); dd[2*j] = u.x; dd[2*j+1] = u.y;
    }
    float mu = 0.f;
    #pragma unroll
    for (int l = 0; l < NN; l++) mu += a[l];
    mu *= (1.f/NN);
    float s2 = 0.f;
    #pragma unroll
    for (int l = 0; l < NN; l++){ float d = a[l]-mu; s2 += d*d; }
    float rs = rsqrtf(s2*(1.f/NN) + 1e-5f);
    float* dst = g_y1 + (size_t)b*NN*512;
    #pragma unroll
    for (int l = 0; l < NN; l++){
        float v = (a[l]-mu)*rs*__ldg(&lnw[l]) + __ldg(&lnb[l]);
        v = v > 0.f ? v : 0.f;
        dst[l*512 + co] = v + dd[l];
    }
}

// ---- TCN block 2: 512->256, dil 4, 1x1 downsample. smem transposed [ci][42] ----
__global__ __launch_bounds__(256) void k_tcn2(const float* __restrict__ b2, const float* __restrict__ dsb,
    const float* __restrict__ lnw, const float* __restrict__ lnb)
{
    extern __shared__ __align__(16) float hsp2[];   // 512*42 floats = 86016 B
    const int b = blockIdx.x, tid = threadIdx.x;
    for (int i = tid; i < 512*42; i += 256) hsp2[i] = 0.f;
    __syncthreads();
    const float* src = g_y1 + (size_t)b*NN*512;
    for (int idx = tid; idx < NN*512; idx += 256){
        int l = idx >> 9, c = idx & 511;
        hsp2[c*42 + l + 4] = src[idx];
    }
    __syncthreads();
    const int co = tid;
    u64 acc2[15], accd2[15];
    {
        u64 bb = dup2(b2[co]), bd = dup2(dsb[co]);
        #pragma unroll
        for (int j = 0; j < 15; j++){ acc2[j] = bb; accd2[j] = bd; }
    }
    for (int ci = 0; ci < 512; ci++){
        const float* row = &hsp2[ci*42];
        u64 w0d = dup2(g_w2t[(ci*3+0)*256 + co]);
        u64 w1d = dup2(g_w2t[(ci*3+1)*256 + co]);
        u64 w2d = dup2(g_w2t[(ci*3+2)*256 + co]);
        u64 wdd = dup2(g_ds2t[ci*256 + co]);
        u64 Ew0 = *(const u64*)(row);
        u64 Ew1 = *(const u64*)(row + 2);
        u64 Ew2 = *(const u64*)(row + 4);
        u64 Ew3 = *(const u64*)(row + 6);
        #pragma unroll
        for (int j = 0; j < 15; j++){
            u64 Ew4 = *(const u64*)(row + 2*j + 8);
            fma2(acc2[j], w0d, Ew0);
            fma2(acc2[j], w1d, Ew2);
            fma2(acc2[j], w2d, Ew4);
            fma2(accd2[j], wdd, Ew2);
            Ew0 = Ew1; Ew1 = Ew2; Ew2 = Ew3; Ew3 = Ew4;
        }
    }
    float a[NN], dd[NN];
    #pragma unroll
    for (int j = 0; j < 15; j++){
        float2 t = unp2(acc2[j]);  a[2*j] = t.x;  a[2*j+1] = t.y;
        float2 u = unp2(accd2[j]); dd[2*j] = u.x; dd[2*j+1] = u.y;
    }
    float mu = 0.f;
    #pragma unroll
    for (int l = 0; l < NN; l++) mu += a[l];
    mu *= (1.f/NN);
    float s2 = 0.f;
    #pragma unroll
    for (int l = 0; l < NN; l++){ float d = a[l]-mu; s2 += d*d; }
    float rs = rsqrtf(s2*(1.f/NN) + 1e-5f);
    float* dst = g_y2 + (size_t)b*NN*256;
    #pragma unroll
    for (int l = 0; l < NN; l++){
        float v = (a[l]-mu)*rs*__ldg(&lnw[l]) + __ldg(&lnb[l]);
        v = v > 0.f ? v : 0.f;
        dst[l*256 + co] = v + dd[l];
    }
}

// ---- tiled GEMM body ----
__device__ __forceinline__ void gemm_body(const float* __restrict__ A, const float* __restrict__ Bw,
    const float* __restrict__ bias, float* __restrict__ C, int M, int N, int K, bool doRelu)
{
    __shared__ __align__(16) float As2[16][68];
    __shared__ __align__(16) float Bs2[16][68];
    const int tid = threadIdx.x;
    const int tx = tid & 15, ty = tid >> 4;
    const int m0 = blockIdx.y*64, n0 = blockIdx.x*64;
    const int lm = tid >> 2, lk = (tid & 3)*4;
    float acc[4][4];
    #pragma unroll
    for (int i = 0; i < 4; i++)
        #pragma unroll
        for (int j = 0; j < 4; j++) acc[i][j] = 0.f;

    for (int k0 = 0; k0 < K; k0 += 16){
        float4 av = *(const float4*)&A[(size_t)(m0+lm)*K + k0 + lk];
        float4 bv = make_float4(0.f,0.f,0.f,0.f);
        if (n0 + lm < N) bv = *(const float4*)&Bw[(size_t)(n0+lm)*K + k0 + lk];
        As2[lk+0][lm] = av.x; As2[lk+1][lm] = av.y; As2[lk+2][lm] = av.z; As2[lk+3][lm] = av.w;
        Bs2[lk+0][lm] = bv.x; Bs2[lk+1][lm] = bv.y; Bs2[lk+2][lm] = bv.z; Bs2[lk+3][lm] = bv.w;
        __syncthreads();
        #pragma unroll
        for (int k = 0; k < 16; k++){
            float4 a  = *(const float4*)&As2[k][ty*4];
            float4 bb = *(const float4*)&Bs2[k][tx*4];
            acc[0][0] += a.x*bb.x; acc[0][1] += a.x*bb.y; acc[0][2] += a.x*bb.z; acc[0][3] += a.x*bb.w;
            acc[1][0] += a.y*bb.x; acc[1][1] += a.y*bb.y; acc[1][2] += a.y*bb.z; acc[1][3] += a.y*bb.w;
            acc[2][0] += a.z*bb.x; acc[2][1] += a.z*bb.y; acc[2][2] += a.z*bb.z; acc[2][3] += a.z*bb.w;
            acc[3][0] += a.w*bb.x; acc[3][1] += a.w*bb.y; acc[3][2] += a.w*bb.z; acc[3][3] += a.w*bb.w;
        }
        __syncthreads();
    }
    #pragma unroll
    for (int i = 0; i < 4; i++){
        int row = m0 + ty*4 + i;
        #pragma unroll
        for (int j = 0; j < 4; j++){
            int col = n0 + tx*4 + j;
            if (col < N){
                float v = acc[i][j] + __ldg(&bias[col]);
                if (doRelu) v = v > 0.f ? v : 0.f;
                C[(size_t)row*N + col] = v;
            }
        }
    }
}
__global__ __launch_bounds__(256) void k_fc1(const float* __restrict__ bias){
    gemm_body(g_y2, g_fc1p, bias, g_z1, 1024, 512, 7680, true);
}
__global__ __launch_bounds__(256) void k_fc2(const float* __restrict__ w, const float* __restrict__ bias){
    gemm_body(g_z1, w, bias, g_z2, 1024, 256, 512, true);
}
__global__ __launch_bounds__(256) void k_fc3(const float* __restrict__ w, const float* __restrict__ bias,
                                             float* __restrict__ out){
    gemm_body(g_z2, w, bias, out, 1024, 144, 256, false);
}

extern "C" void kernel_launch(void* const* d_in, const int* in_sizes, int n_in,
                              void* d_out, int out_size) {
    const float* x      = (const float*)d_in[0];
    const float* gWl    = (const float*)d_in[1];
    const float* gbl    = (const float*)d_in[2];
    const float* gWr    = (const float*)d_in[3];
    const float* gbr    = (const float*)d_in[4];
    const float* gatt   = (const float*)d_in[5];
    const float* gbias  = (const float*)d_in[6];
    const float* t0w    = (const float*)d_in[7];
    const float* t0b    = (const float*)d_in[8];
    const float* ln0w   = (const float*)d_in[9];
    const float* ln0b   = (const float*)d_in[10];
    const float* t1w    = (const float*)d_in[11];
    const float* t1b    = (const float*)d_in[12];
    const float* ln1w   = (const float*)d_in[13];
    const float* ln1b   = (const float*)d_in[14];
    const float* ds1w   = (const float*)d_in[15];
    const float* ds1b   = (const float*)d_in[16];
    const float* t2w    = (const float*)d_in[17];
    const float* t2b    = (const float*)d_in[18];
    const float* ln2w   = (const float*)d_in[19];
    const float* ln2b   = (const float*)d_in[20];
    const float* ds2w   = (const float*)d_in[21];
    const float* ds2b   = (const float*)d_in[22];
    const float* fc1w   = (const float*)d_in[23];
    const float* fc1b   = (const float*)d_in[24];
    const float* fc2w   = (const float*)d_in[25];
    const float* fc2b   = (const float*)d_in[26];
    const float* fc3w   = (const float*)d_in[27];
    const float* fc3b   = (const float*)d_in[28];
    const int*   eidx   = (const int*)d_in[29];

    float* outp = (float*)d_out;
    bool full = (out_size >= 147456 + ETOT*4 + 2*ETOT);
    float* alphaOut = full ? (outp + 147456) : nullptr;
    float* eiOut    = full ? (outp + 147456 + ETOT*4) : nullptr;

    cudaFuncSetAttribute(k_gat,  cudaFuncAttributeMaxDynamicSharedMemorySize, 84*1024);
    cudaFuncSetAttribute(k_tcn2, cudaFuncAttributeMaxDynamicSharedMemorySize, 512*42*4);

    k_tr_wlr<<<64,256>>>(gWl, gWr);
    k_tr_w0 <<<768,256>>>(t0w);
    k_tr_w1 <<<1536,256>>>(t1w);
    k_tr_ds1<<<512,256>>>(ds1w);
    k_tr_w2 <<<1536,256>>>(t2w);
    k_tr_ds2<<<512,256>>>(ds2w);
    k_tr_fc1<<<15360,256>>>(fc1w);
    if (eiOut) k_ei<<<1080,256>>>(eidx, eiOut);

    k_gat<<<1024,256, 84*1024>>>(x, gbl, gbr, gatt, gbias, eidx, alphaOut);
    k_tcn0<<<1024,256>>>(t0b, ln0w, ln0b);
    k_tcn1<<<1024,512>>>(t1b, ds1b, ln1w, ln1b);
    k_tcn2<<<1024,256, 512*42*4>>>(t2b, ds2b, ln2w, ln2b);

    dim3 g1(8,16);  k_fc1<<<g1,256>>>(fc1b);
    dim3 g2(4,16);  k_fc2<<<g2,256>>>(fc2w, fc2b);
    dim3 g3(3,16);  k_fc3<<<g3,256>>>(fc3w, fc3b, outp);
}

// round 6
// speedup vs baseline: 2.1569x; 1.1154x over previous
#include <cuda_runtime.h>

#define NN 30
#define EPG 240
#define NEDGE 245760
#define ETOT  276480

typedef unsigned long long u64;

__device__ float g_h [30720*256];
__device__ float g_y0[30720*256];
__device__ float g_y1[30720*512];
__device__ float g_y2[30720*256];
__device__ float g_z1[1024*512];
__device__ float g_z2[1024*256];
__device__ float g_wlt[64*256];
__device__ float g_wrt[64*256];
__device__ float g_w0t[768*256];
__device__ float g_w1t[768*512];
__device__ float g_ds1t[256*512];
__device__ float g_w2t[1536*256];
__device__ float g_ds2t[512*256];
__device__ float g_fc1p[512*7680];

__device__ __forceinline__ unsigned ford(float f){
    unsigned u = __float_as_uint(f);
    return (u & 0x80000000u) ? ~u : (u | 0x80000000u);
}
__device__ __forceinline__ float finv(unsigned u){
    return __uint_as_float((u & 0x80000000u) ? (u & 0x7fffffffu) : ~u);
}

// ---- f32x2 helpers ----
__device__ __forceinline__ u64 dup2(float v){
    u64 r; asm("mov.b64 %0, {%1, %1};" : "=l"(r) : "f"(v)); return r;
}
__device__ __forceinline__ float2 unp2(u64 v){
    float2 r; asm("mov.b64 {%0, %1}, %2;" : "=f"(r.x), "=f"(r.y) : "l"(v)); return r;
}
__device__ __forceinline__ void fma2(u64& a, u64 b, u64 c){
    asm("fma.rn.f32x2 %0, %1, %2, %0;" : "+l"(a) : "l"(b), "l"(c));
}

// ---- tf32 helpers ----
__device__ __forceinline__ float tf32r(float f){
    unsigned u; asm("cvt.rna.tf32.f32 %0, %1;" : "=r"(u) : "f"(f));
    return __uint_as_float(u);
}
__device__ __forceinline__ void mma8(float* d, const unsigned* a, unsigned b0, unsigned b1){
    asm("mma.sync.aligned.m16n8k8.row.col.f32.tf32.tf32.f32 "
        "{%0,%1,%2,%3},{%4,%5,%6,%7},{%8,%9},{%0,%1,%2,%3};"
        : "+f"(d[0]),"+f"(d[1]),"+f"(d[2]),"+f"(d[3])
        : "r"(a[0]),"r"(a[1]),"r"(a[2]),"r"(a[3]),"r"(b0),"r"(b1));
}

// ---- weight prep (tap-major [t*CIN+ci][co], tf32-rounded for TCN) ----
__global__ void k_tr_wlr(const float* __restrict__ wl, const float* __restrict__ wr){
    int i = blockIdx.x*256 + threadIdx.x;
    if (i < 64*256){ int c = i>>6, k = i&63; g_wlt[k*256+c] = wl[i]; g_wrt[k*256+c] = wr[i]; }
}
__global__ void k_tr_w0(const float* __restrict__ w){
    int i = blockIdx.x*256 + threadIdx.x;
    if (i < 256*768){
        int co = i/768, rem = i - co*768, ci = rem/3, t = rem - ci*3;
        g_w0t[(t*256+ci)*256 + co] = tf32r(w[i]);
    }
}
__global__ void k_tr_w1(const float* __restrict__ w){
    int i = blockIdx.x*256 + threadIdx.x;
    if (i < 512*768){
        int co = i/768, rem = i - co*768, ci = rem/3, t = rem - ci*3;
        g_w1t[(t*256+ci)*512 + co] = tf32r(w[i]);
    }
}
__global__ void k_tr_ds1(const float* __restrict__ w){
    int i = blockIdx.x*256 + threadIdx.x;
    if (i < 512*256){ int co = i>>8, ci = i&255; g_ds1t[ci*512+co] = tf32r(w[i]); }
}
__global__ void k_tr_w2(const float* __restrict__ w){
    int i = blockIdx.x*256 + threadIdx.x;
    if (i < 256*1536){
        int co = i/1536, rem = i - co*1536, ci = rem/3, t = rem - ci*3;
        g_w2t[(t*512+ci)*256 + co] = tf32r(w[i]);
    }
}
__global__ void k_tr_ds2(const float* __restrict__ w){
    int i = blockIdx.x*256 + threadIdx.x;
    if (i < 256*512){ int co = i>>9, ci = i&511; g_ds2t[ci*256+co] = tf32r(w[i]); }
}
__global__ void k_tr_fc1(const float* __restrict__ w){
    int i = blockIdx.x*256 + threadIdx.x;
    if (i < 512*7680){
        int o = i/7680, kp = i - o*7680;
        int l = kp>>8, c = kp&255;
        g_fc1p[i] = w[o*7680 + c*30 + l];
    }
}
__global__ void k_ei(const int* __restrict__ eidx, float* __restrict__ eo){
    int e = blockIdx.x*256 + threadIdx.x;
    if (e < ETOT){
        float s, d;
        if (e < NEDGE){ s = (float)eidx[e]; d = (float)eidx[NEDGE+e]; }
        else          { s = d = (float)(e - NEDGE); }
        eo[e] = s; eo[ETOT + e] = d;
    }
}

// ---- GATv2 per graph (unchanged, fp32) ----
__global__ __launch_bounds__(256) void k_gat(
    const float* __restrict__ x, const float* __restrict__ bl, const float* __restrict__ br,
    const float* __restrict__ att, const float* __restrict__ bias,
    const int* __restrict__ eidx, float* __restrict__ alphaOut)
{
    extern __shared__ float sm[];
    float*    xs    = sm;
    float*    xl    = xs + 1920;
    float*    xr    = xl + 7680;
    float*    atts  = xr + 7680;
    float*    ea    = atts + 256;
    float*    esum  = ea + 1088;
    unsigned* emaxu = (unsigned*)(esum + 120);
    int*      srcs  = (int*)(emaxu + 120);
    int*      dsts  = srcs + 272;
    int*      cnt   = dsts + 272;
    int*      lists = cnt + 32;

    const int b = blockIdx.x, tid = threadIdx.x;

    {
        const float4* s4 = (const float4*)(x + (size_t)b*NN*64);
        float4* d4 = (float4*)xs;
        for (int i = tid; i < 480; i += 256) d4[i] = s4[i];
    }
    atts[tid] = att[tid];
    for (int i = tid; i < 120; i += 256){ emaxu[i] = 0u; esum[i] = 0.f; }
    if (tid < 30) cnt[tid] = 0;
    for (int j = tid; j < 270; j += 256){
        int s, d;
        if (j < EPG){
            s = eidx[(size_t)b*EPG + j] - b*NN;
            d = eidx[NEDGE + (size_t)b*EPG + j] - b*NN;
        } else { s = d = j - EPG; }
        srcs[j] = s; dsts[j] = d;
    }
    __syncthreads();

    {
        const int c = tid;
        float accl[NN], accr[NN];
        float blv = bl[c], brv = br[c];
        #pragma unroll
        for (int n = 0; n < NN; n++){ accl[n] = blv; accr[n] = brv; }
        for (int k0 = 0; k0 < 64; k0 += 8){
            float wlv[8], wrv[8];
            #pragma unroll
            for (int kk = 0; kk < 8; kk++){
                wlv[kk] = g_wlt[(k0+kk)*256 + c];
                wrv[kk] = g_wrt[(k0+kk)*256 + c];
            }
            #pragma unroll
            for (int n = 0; n < NN; n++){
                #pragma unroll
                for (int kk = 0; kk < 8; kk++){
                    float xv = xs[n*64 + k0 + kk];
                    accl[n] += xv * wlv[kk];
                    accr[n] += xv * wrv[kk];
                }
            }
        }
        #pragma unroll
        for (int n = 0; n < NN; n++){ xl[n*256+c] = accl[n]; xr[n*256+c] = accr[n]; }
    }
    __syncthreads();

    {
        const int warp = tid >> 5, lane = tid & 31;
        const int h4 = lane >> 3, chb = lane * 8;
        for (int e = warp; e < 270; e += 8){
            const float* pl = &xl[srcs[e]*256 + chb];
            const float* pr = &xr[dsts[e]*256 + chb];
            float p = 0.f;
            #pragma unroll
            for (int i = 0; i < 8; i++){
                float v = pl[i] + pr[i];
                v = v > 0.f ? v : 0.2f*v;
                p += v * atts[chb + i];
            }
            p += __shfl_down_sync(0xffffffffu, p, 4, 8);
            p += __shfl_down_sync(0xffffffffu, p, 2, 8);
            p += __shfl_down_sync(0xffffffffu, p, 1, 8);
            if ((lane & 7) == 0) ea[e*4 + h4] = p;
        }
    }
    __syncthreads();

    for (int it = tid; it < 1080; it += 256){
        int e = it >> 2, h = it & 3;
        atomicMax(&emaxu[dsts[e]*4 + h], ford(ea[it]));
    }
    __syncthreads();
    for (int it = tid; it < 1080; it += 256){
        int e = it >> 2, h = it & 3; int d = dsts[e];
        float ex = __expf(ea[it] - finv(emaxu[d*4 + h]));
        ea[it] = ex;
        atomicAdd(&esum[d*4 + h], ex);
    }
    __syncthreads();
    for (int it = tid; it < 1080; it += 256){
        int e = it >> 2, h = it & 3;
        float a = ea[it] / esum[dsts[e]*4 + h];
        ea[it] = a;
        if (alphaOut){
            int grow = (e < EPG) ? (b*EPG + e) : (NEDGE + b*NN + (e - EPG));
            alphaOut[(size_t)grow*4 + h] = a;
        }
    }
    for (int e = tid; e < 270; e += 256){
        int d = dsts[e];
        int slot = atomicAdd(&cnt[d], 1);
        if (slot < 48) lists[d*48 + slot] = e;
    }
    __syncthreads();

    {
        const int c = tid, hh = c >> 6;
        float bv = bias[c];
        for (int n = 0; n < NN; n++){
            float a = 0.f;
            int deg = cnt[n]; if (deg > 48) deg = 48;
            for (int i = 0; i < deg; i++){
                int e = lists[n*48 + i];
                a += ea[e*4 + hh] * xl[srcs[e]*256 + c];
            }
            float v = a + bv;
            g_h[((size_t)(b*NN + n))*256 + c] = v > 0.f ? v : 0.f;
        }
    }
}

// ==================== TF32 mma TCN block ====================
// GEMM view per CTA (2 graphs): C[64 x COUT] = A[64 x 3*CIN] @ W[3*CIN x COUT]
// A row m = (graph, l) with l in 0..31 (30,31 garbage, discarded).
// A[(g,l)][(t,ci)] = hsp[g][ci][DIL*t + l]   (hsp padded row R=40, zero halo)
// + optional downsample pass (K=CIN, center tap) into Cds.
template<int CIN, int COUT, int DIL, int NCHUNK, bool HAS_DS>
__device__ __forceinline__ void tcn_mma(
    const float* __restrict__ srcY, const float* __restrict__ Wt, const float* __restrict__ Wds,
    const float* __restrict__ bias, const float* __restrict__ dsb,
    const float* __restrict__ lnw, const float* __restrict__ lnb,
    const float* __restrict__ resSrc, float* __restrict__ dstY)
{
    const int R = 40;
    const int CPAD = NCHUNK + 1;
    const int NT = NCHUNK/64;          // n8-tiles per warp (8 warps)
    const int KS = CIN/8;
    extern __shared__ float smem[];
    float* hsp = smem;                 // 2*CIN*R
    float* Cc  = smem + 2*CIN*R;       // 64*CPAD
    float* Cds = Cc + 64*CPAD;         // 64*CPAD (only if HAS_DS)

    const int tid  = threadIdx.x;
    const int warp = tid >> 5, lane = tid & 31;
    const int g = lane >> 2, tig = lane & 3;
    const int b0g = blockIdx.x*2;

    for (int i = tid; i < 2*CIN*R; i += 256) hsp[i] = 0.f;
    __syncthreads();
    for (int idx = tid; idx < 2*30*CIN; idx += 256){
        int gg = idx / (30*CIN); int r = idx - gg*30*CIN;
        int l = r / CIN, c = r - l*CIN;
        hsp[(gg*CIN + c)*R + DIL + l] = tf32r(srcY[((size_t)((b0g+gg)*30) + l)*CIN + c]);
    }
    __syncthreads();

    for (int chunk = 0; chunk < COUT/NCHUNK; chunk++){
        const int nbase = chunk*NCHUNK + warp*(NCHUNK/8);
        float acc[4][NT][4];
        #pragma unroll
        for (int mt=0; mt<4; mt++)
            #pragma unroll
            for (int nt=0; nt<NT; nt++)
                #pragma unroll
                for (int q=0; q<4; q++) acc[mt][nt][q] = 0.f;

        #pragma unroll
        for (int t = 0; t < 3; t++){
            const float* Wk = Wt + (size_t)(t*CIN)*COUT + nbase;
            const int aoff = DIL*t;
            for (int kk = 0; kk < KS; kk++){
                unsigned A[4][4];
                #pragma unroll
                for (int mt=0; mt<4; mt++){
                    const float* base = &hsp[((mt>>1)*CIN + kk*8 + tig)*R + aoff + (mt&1)*16 + g];
                    A[mt][0] = __float_as_uint(base[0]);
                    A[mt][1] = __float_as_uint(base[8]);
                    A[mt][2] = __float_as_uint(base[4*R]);
                    A[mt][3] = __float_as_uint(base[4*R + 8]);
                }
                const float* Wrow = Wk + (size_t)kk*8*COUT;
                #pragma unroll
                for (int nt=0; nt<NT; nt++){
                    unsigned br0 = __float_as_uint(__ldg(&Wrow[tig*COUT + nt*8 + g]));
                    unsigned br1 = __float_as_uint(__ldg(&Wrow[(tig+4)*COUT + nt*8 + g]));
                    #pragma unroll
                    for (int mt=0; mt<4; mt++) mma8(acc[mt][nt], A[mt], br0, br1);
                }
            }
        }
        __syncthreads();   // previous chunk's epilogue finished reading Cc/Cds
        #pragma unroll
        for (int mt=0; mt<4; mt++)
            #pragma unroll
            for (int nt=0; nt<NT; nt++){
                int r0 = mt*16 + g;
                int cb = warp*(NCHUNK/8) + nt*8 + 2*tig;
                Cc[r0*CPAD + cb]       = acc[mt][nt][0];
                Cc[r0*CPAD + cb + 1]   = acc[mt][nt][1];
                Cc[(r0+8)*CPAD + cb]   = acc[mt][nt][2];
                Cc[(r0+8)*CPAD + cb+1] = acc[mt][nt][3];
            }
        if (HAS_DS){
            #pragma unroll
            for (int mt=0; mt<4; mt++)
                #pragma unroll
                for (int nt=0; nt<NT; nt++)
                    #pragma unroll
                    for (int q=0; q<4; q++) acc[mt][nt][q] = 0.f;
            const float* Wk = Wds + nbase;
            for (int kk = 0; kk < KS; kk++){
                unsigned A[4][4];
                #pragma unroll
                for (int mt=0; mt<4; mt++){
                    const float* base = &hsp[((mt>>1)*CIN + kk*8 + tig)*R + DIL + (mt&1)*16 + g];
                    A[mt][0] = __float_as_uint(base[0]);
                    A[mt][1] = __float_as_uint(base[8]);
                    A[mt][2] = __float_as_uint(base[4*R]);
                    A[mt][3] = __float_as_uint(base[4*R + 8]);
                }
                const float* Wrow = Wk + (size_t)kk*8*COUT;
                #pragma unroll
                for (int nt=0; nt<NT; nt++){
                    unsigned br0 = __float_as_uint(__ldg(&Wrow[tig*COUT + nt*8 + g]));
                    unsigned br1 = __float_as_uint(__ldg(&Wrow[(tig+4)*COUT + nt*8 + g]));
                    #pragma unroll
                    for (int mt=0; mt<4; mt++) mma8(acc[mt][nt], A[mt], br0, br1);
                }
            }
            #pragma unroll
            for (int mt=0; mt<4; mt++)
                #pragma unroll
                for (int nt=0; nt<NT; nt++){
                    int r0 = mt*16 + g;
                    int cb = warp*(NCHUNK/8) + nt*8 + 2*tig;
                    Cds[r0*CPAD + cb]       = acc[mt][nt][0];
                    Cds[r0*CPAD + cb + 1]   = acc[mt][nt][1];
                    Cds[(r0+8)*CPAD + cb]   = acc[mt][nt][2];
                    Cds[(r0+8)*CPAD + cb+1] = acc[mt][nt][3];
                }
        }
        __syncthreads();
        // ---- epilogue: per-column LayerNorm + relu + residual ----
        {
            const int passes  = (NCHUNK == 256) ? 2 : 1;
            const int ggbase  = (NCHUNK == 256) ? 0 : (tid >> 7);
            const int col     = (NCHUNK == 256) ? tid : (tid & 127);
            for (int p = 0; p < passes; p++){
                int gg = ggbase + p;
                int cg = chunk*NCHUNK + col;
                float bv = __ldg(&bias[cg]);
                float v[NN];
                float mu = 0.f;
                #pragma unroll
                for (int l = 0; l < NN; l++){
                    v[l] = Cc[(gg*32 + l)*CPAD + col] + bv;
                    mu += v[l];
                }
                mu *= (1.f/NN);
                float s2 = 0.f;
                #pragma unroll
                for (int l = 0; l < NN; l++){ float d = v[l]-mu; s2 += d*d; }
                float rs = rsqrtf(s2*(1.f/NN) + 1e-5f);
                float dbv = HAS_DS ? __ldg(&dsb[cg]) : 0.f;
                #pragma unroll
                for (int l = 0; l < NN; l++){
                    float o = (v[l]-mu)*rs*__ldg(&lnw[l]) + __ldg(&lnb[l]);
                    o = o > 0.f ? o : 0.f;
                    float rr;
                    if (HAS_DS) rr = Cds[(gg*32 + l)*CPAD + col] + dbv;
                    else        rr = resSrc[((size_t)((b0g+gg)*30) + l)*COUT + cg];
                    dstY[((size_t)((b0g+gg)*30) + l)*COUT + cg] = o + rr;
                }
            }
        }
    }
}

__global__ __launch_bounds__(256) void k_tcn0m(const float* __restrict__ b0,
    const float* __restrict__ lnw, const float* __restrict__ lnb){
    tcn_mma<256,256,1,256,false>(g_h, g_w0t, nullptr, b0, nullptr, lnw, lnb, g_h, g_y0);
}
__global__ __launch_bounds__(256) void k_tcn1m(const float* __restrict__ b1, const float* __restrict__ dsb,
    const float* __restrict__ lnw, const float* __restrict__ lnb){
    tcn_mma<256,512,2,256,true>(g_y0, g_w1t, g_ds1t, b1, dsb, lnw, lnb, nullptr, g_y1);
}
__global__ __launch_bounds__(256) void k_tcn2m(const float* __restrict__ b2, const float* __restrict__ dsb,
    const float* __restrict__ lnw, const float* __restrict__ lnb){
    tcn_mma<512,256,4,128,true>(g_y1, g_w2t, g_ds2t, b2, dsb, lnw, lnb, nullptr, g_y2);
}

// ---- tiled GEMM body (f32x2): C[M,N] = act(A[M,K] @ Bw[N,K]^T + bias) ----
__device__ __forceinline__ void gemm_body(const float* __restrict__ A, const float* __restrict__ Bw,
    const float* __restrict__ bias, float* __restrict__ C, int M, int N, int K, bool doRelu)
{
    __shared__ __align__(16) float As2[16][68];
    __shared__ __align__(16) float Bs2[16][68];
    const int tid = threadIdx.x;
    const int tx = tid & 15, ty = tid >> 4;
    const int m0 = blockIdx.y*64, n0 = blockIdx.x*64;
    const int lm = tid >> 2, lk = (tid & 3)*4;
    u64 acc2[4][2];
    #pragma unroll
    for (int i = 0; i < 4; i++){ acc2[i][0] = 0ull; acc2[i][1] = 0ull; }

    for (int k0 = 0; k0 < K; k0 += 16){
        float4 av = *(const float4*)&A[(size_t)(m0+lm)*K + k0 + lk];
        float4 bv = make_float4(0.f,0.f,0.f,0.f);
        if (n0 + lm < N) bv = *(const float4*)&Bw[(size_t)(n0+lm)*K + k0 + lk];
        As2[lk+0][lm] = av.x; As2[lk+1][lm] = av.y; As2[lk+2][lm] = av.z; As2[lk+3][lm] = av.w;
        Bs2[lk+0][lm] = bv.x; Bs2[lk+1][lm] = bv.y; Bs2[lk+2][lm] = bv.z; Bs2[lk+3][lm] = bv.w;
        __syncthreads();
        #pragma unroll
        for (int k = 0; k < 16; k++){
            float4 a = *(const float4*)&As2[k][ty*4];
            u64 bp0 = *(const u64*)&Bs2[k][tx*4];
            u64 bp1 = *(const u64*)&Bs2[k][tx*4+2];
            u64 a0 = dup2(a.x), a1 = dup2(a.y), a2 = dup2(a.z), a3 = dup2(a.w);
            fma2(acc2[0][0], a0, bp0); fma2(acc2[0][1], a0, bp1);
            fma2(acc2[1][0], a1, bp0); fma2(acc2[1][1], a1, bp1);
            fma2(acc2[2][0], a2, bp0); fma2(acc2[2][1], a2, bp1);
            fma2(acc2[3][0], a3, bp0); fma2(acc2[3][1], a3, bp1);
        }
        __syncthreads();
    }
    #pragma unroll
    for (int i = 0; i < 4; i++){
        int row = m0 + ty*4 + i;
        float2 p0 = unp2(acc2[i][0]), p1 = unp2(acc2[i][1]);
        float vals[4] = {p0.x, p0.y, p1.x, p1.y};
        #pragma unroll
        for (int j = 0; j < 4; j++){
            int col = n0 + tx*4 + j;
            if (col < N){
                float v = vals[j] + __ldg(&bias[col]);
                if (doRelu) v = v > 0.f ? v : 0.f;
                C[(size_t)row*N + col] = v;
            }
        }
    }
}
__global__ __launch_bounds__(256) void k_fc1(const float* __restrict__ bias){
    gemm_body(g_y2, g_fc1p, bias, g_z1, 1024, 512, 7680, true);
}
__global__ __launch_bounds__(256) void k_fc2(const float* __restrict__ w, const float* __restrict__ bias){
    gemm_body(g_z1, w, bias, g_z2, 1024, 256, 512, true);
}
__global__ __launch_bounds__(256) void k_fc3(const float* __restrict__ w, const float* __restrict__ bias,
                                             float* __restrict__ out){
    gemm_body(g_z2, w, bias, out, 1024, 144, 256, false);
}

extern "C" void kernel_launch(void* const* d_in, const int* in_sizes, int n_in,
                              void* d_out, int out_size) {
    const float* x      = (const float*)d_in[0];
    const float* gWl    = (const float*)d_in[1];
    const float* gbl    = (const float*)d_in[2];
    const float* gWr    = (const float*)d_in[3];
    const float* gbr    = (const float*)d_in[4];
    const float* gatt   = (const float*)d_in[5];
    const float* gbias  = (const float*)d_in[6];
    const float* t0w    = (const float*)d_in[7];
    const float* t0b    = (const float*)d_in[8];
    const float* ln0w   = (const float*)d_in[9];
    const float* ln0b   = (const float*)d_in[10];
    const float* t1w    = (const float*)d_in[11];
    const float* t1b    = (const float*)d_in[12];
    const float* ln1w   = (const float*)d_in[13];
    const float* ln1b   = (const float*)d_in[14];
    const float* ds1w   = (const float*)d_in[15];
    const float* ds1b   = (const float*)d_in[16];
    const float* t2w    = (const float*)d_in[17];
    const float* t2b    = (const float*)d_in[18];
    const float* ln2w   = (const float*)d_in[19];
    const float* ln2b   = (const float*)d_in[20];
    const float* ds2w   = (const float*)d_in[21];
    const float* ds2b   = (const float*)d_in[22];
    const float* fc1w   = (const float*)d_in[23];
    const float* fc1b   = (const float*)d_in[24];
    const float* fc2w   = (const float*)d_in[25];
    const float* fc2b   = (const float*)d_in[26];
    const float* fc3w   = (const float*)d_in[27];
    const float* fc3b   = (const float*)d_in[28];
    const int*   eidx   = (const int*)d_in[29];

    float* outp = (float*)d_out;
    bool full = (out_size >= 147456 + ETOT*4 + 2*ETOT);
    float* alphaOut = full ? (outp + 147456) : nullptr;
    float* eiOut    = full ? (outp + 147456 + ETOT*4) : nullptr;

    // smem byte sizes for the mma tcn kernels
    const int SM0 = (2*256*40 + 64*257) * 4;              // 147,712
    const int SM1 = (2*256*40 + 2*64*257) * 4;            // 213,504
    const int SM2 = (2*512*40 + 2*64*129) * 4;            // 229,888

    cudaFuncSetAttribute(k_gat,   cudaFuncAttributeMaxDynamicSharedMemorySize, 84*1024);
    cudaFuncSetAttribute(k_tcn0m, cudaFuncAttributeMaxDynamicSharedMemorySize, SM0);
    cudaFuncSetAttribute(k_tcn1m, cudaFuncAttributeMaxDynamicSharedMemorySize, SM1);
    cudaFuncSetAttribute(k_tcn2m, cudaFuncAttributeMaxDynamicSharedMemorySize, SM2);

    k_tr_wlr<<<64,256>>>(gWl, gWr);
    k_tr_w0 <<<768,256>>>(t0w);
    k_tr_w1 <<<1536,256>>>(t1w);
    k_tr_ds1<<<512,256>>>(ds1w);
    k_tr_w2 <<<1536,256>>>(t2w);
    k_tr_ds2<<<512,256>>>(ds2w);
    k_tr_fc1<<<15360,256>>>(fc1w);
    if (eiOut) k_ei<<<1080,256>>>(eidx, eiOut);

    k_gat<<<1024,256, 84*1024>>>(x, gbl, gbr, gatt, gbias, eidx, alphaOut);
    k_tcn0m<<<512,256, SM0>>>(t0b, ln0w, ln0b);
    k_tcn1m<<<512,256, SM1>>>(t1b, ds1b, ln1w, ln1b);
    k_tcn2m<<<512,256, SM2>>>(t2b, ds2b, ln2w, ln2b);

    dim3 g1(8,16);  k_fc1<<<g1,256>>>(fc1b);
    dim3 g2(4,16);  k_fc2<<<g2,256>>>(fc2w, fc2b);
    dim3 g3(3,16);  k_fc3<<<g3,256>>>(fc3w, fc3b, outp);
}

// round 7
// speedup vs baseline: 2.4794x; 1.1495x over previous
#include <cuda_runtime.h>

#define NN 30
#define EPG 240
#define NEDGE 245760
#define ETOT  276480

typedef unsigned long long u64;

__device__ float g_h [30720*256];
__device__ float g_y0[30720*256];
__device__ float g_y1[30720*512];
__device__ float g_y2[30720*256];
__device__ float g_z1[1024*512];
__device__ float g_z2[1024*256];
__device__ float g_wlt[64*256];
__device__ float g_wrt[64*256];
__device__ float g_w0t[768*256];
__device__ float g_w1t[768*512];
__device__ float g_ds1t[256*512];
__device__ float g_w2t[1536*256];
__device__ float g_ds2t[512*256];
__device__ float g_fc1p[512*7680];

__device__ __forceinline__ unsigned ford(float f){
    unsigned u = __float_as_uint(f);
    return (u & 0x80000000u) ? ~u : (u | 0x80000000u);
}
__device__ __forceinline__ float finv(unsigned u){
    return __uint_as_float((u & 0x80000000u) ? (u & 0x7fffffffu) : ~u);
}

// ---- f32x2 helpers ----
__device__ __forceinline__ u64 dup2(float v){
    u64 r; asm("mov.b64 %0, {%1, %1};" : "=l"(r) : "f"(v)); return r;
}
__device__ __forceinline__ float2 unp2(u64 v){
    float2 r; asm("mov.b64 {%0, %1}, %2;" : "=f"(r.x), "=f"(r.y) : "l"(v)); return r;
}
__device__ __forceinline__ void fma2(u64& a, u64 b, u64 c){
    asm("fma.rn.f32x2 %0, %1, %2, %0;" : "+l"(a) : "l"(b), "l"(c));
}

// ---- tf32 helpers ----
__device__ __forceinline__ float tf32r(float f){
    unsigned u; asm("cvt.rna.tf32.f32 %0, %1;" : "=r"(u) : "f"(f));
    return __uint_as_float(u);
}
__device__ __forceinline__ void mma8(float* d, const unsigned* a, unsigned b0, unsigned b1){
    asm("mma.sync.aligned.m16n8k8.row.col.f32.tf32.tf32.f32 "
        "{%0,%1,%2,%3},{%4,%5,%6,%7},{%8,%9},{%0,%1,%2,%3};"
        : "+f"(d[0]),"+f"(d[1]),"+f"(d[2]),"+f"(d[3])
        : "r"(a[0]),"r"(a[1]),"r"(a[2]),"r"(a[3]),"r"(b0),"r"(b1));
}

// ---- weight prep (tap-major [t*CIN+ci][co], tf32-rounded for TCN) ----
__global__ void k_tr_wlr(const float* __restrict__ wl, const float* __restrict__ wr){
    int i = blockIdx.x*256 + threadIdx.x;
    if (i < 64*256){ int c = i>>6, k = i&63; g_wlt[k*256+c] = wl[i]; g_wrt[k*256+c] = wr[i]; }
}
__global__ void k_tr_w0(const float* __restrict__ w){
    int i = blockIdx.x*256 + threadIdx.x;
    if (i < 256*768){
        int co = i/768, rem = i - co*768, ci = rem/3, t = rem - ci*3;
        g_w0t[(t*256+ci)*256 + co] = tf32r(w[i]);
    }
}
__global__ void k_tr_w1(const float* __restrict__ w){
    int i = blockIdx.x*256 + threadIdx.x;
    if (i < 512*768){
        int co = i/768, rem = i - co*768, ci = rem/3, t = rem - ci*3;
        g_w1t[(t*256+ci)*512 + co] = tf32r(w[i]);
    }
}
__global__ void k_tr_ds1(const float* __restrict__ w){
    int i = blockIdx.x*256 + threadIdx.x;
    if (i < 512*256){ int co = i>>8, ci = i&255; g_ds1t[ci*512+co] = tf32r(w[i]); }
}
__global__ void k_tr_w2(const float* __restrict__ w){
    int i = blockIdx.x*256 + threadIdx.x;
    if (i < 256*1536){
        int co = i/1536, rem = i - co*1536, ci = rem/3, t = rem - ci*3;
        g_w2t[(t*512+ci)*256 + co] = tf32r(w[i]);
    }
}
__global__ void k_tr_ds2(const float* __restrict__ w){
    int i = blockIdx.x*256 + threadIdx.x;
    if (i < 256*512){ int co = i>>9, ci = i&511; g_ds2t[ci*256+co] = tf32r(w[i]); }
}
__global__ void k_tr_fc1(const float* __restrict__ w){
    int i = blockIdx.x*256 + threadIdx.x;
    if (i < 512*7680){
        int o = i/7680, kp = i - o*7680;
        int l = kp>>8, c = kp&255;
        g_fc1p[i] = w[o*7680 + c*30 + l];
    }
}
__global__ void k_ei(const int* __restrict__ eidx, float* __restrict__ eo){
    int e = blockIdx.x*256 + threadIdx.x;
    if (e < ETOT){
        float s, d;
        if (e < NEDGE){ s = (float)eidx[e]; d = (float)eidx[NEDGE+e]; }
        else          { s = d = (float)(e - NEDGE); }
        eo[e] = s; eo[ETOT + e] = d;
    }
}

// ---- GATv2 per graph (fp32) ----
__global__ __launch_bounds__(256) void k_gat(
    const float* __restrict__ x, const float* __restrict__ bl, const float* __restrict__ br,
    const float* __restrict__ att, const float* __restrict__ bias,
    const int* __restrict__ eidx, float* __restrict__ alphaOut)
{
    extern __shared__ float sm[];
    float*    xs    = sm;
    float*    xl    = xs + 1920;
    float*    xr    = xl + 7680;
    float*    atts  = xr + 7680;
    float*    ea    = atts + 256;
    float*    esum  = ea + 1088;
    unsigned* emaxu = (unsigned*)(esum + 120);
    int*      srcs  = (int*)(emaxu + 120);
    int*      dsts  = srcs + 272;
    int*      cnt   = dsts + 272;
    int*      lists = cnt + 32;

    const int b = blockIdx.x, tid = threadIdx.x;

    {
        const float4* s4 = (const float4*)(x + (size_t)b*NN*64);
        float4* d4 = (float4*)xs;
        for (int i = tid; i < 480; i += 256) d4[i] = s4[i];
    }
    atts[tid] = att[tid];
    for (int i = tid; i < 120; i += 256){ emaxu[i] = 0u; esum[i] = 0.f; }
    if (tid < 30) cnt[tid] = 0;
    for (int j = tid; j < 270; j += 256){
        int s, d;
        if (j < EPG){
            s = eidx[(size_t)b*EPG + j] - b*NN;
            d = eidx[NEDGE + (size_t)b*EPG + j] - b*NN;
        } else { s = d = j - EPG; }
        srcs[j] = s; dsts[j] = d;
    }
    __syncthreads();

    {
        const int c = tid;
        float accl[NN], accr[NN];
        float blv = bl[c], brv = br[c];
        #pragma unroll
        for (int n = 0; n < NN; n++){ accl[n] = blv; accr[n] = brv; }
        for (int k0 = 0; k0 < 64; k0 += 8){
            float wlv[8], wrv[8];
            #pragma unroll
            for (int kk = 0; kk < 8; kk++){
                wlv[kk] = g_wlt[(k0+kk)*256 + c];
                wrv[kk] = g_wrt[(k0+kk)*256 + c];
            }
            #pragma unroll
            for (int n = 0; n < NN; n++){
                #pragma unroll
                for (int kk = 0; kk < 8; kk++){
                    float xv = xs[n*64 + k0 + kk];
                    accl[n] += xv * wlv[kk];
                    accr[n] += xv * wrv[kk];
                }
            }
        }
        #pragma unroll
        for (int n = 0; n < NN; n++){ xl[n*256+c] = accl[n]; xr[n*256+c] = accr[n]; }
    }
    __syncthreads();

    {
        const int warp = tid >> 5, lane = tid & 31;
        const int h4 = lane >> 3, chb = lane * 8;
        for (int e = warp; e < 270; e += 8){
            const float* pl = &xl[srcs[e]*256 + chb];
            const float* pr = &xr[dsts[e]*256 + chb];
            float p = 0.f;
            #pragma unroll
            for (int i = 0; i < 8; i++){
                float v = pl[i] + pr[i];
                v = v > 0.f ? v : 0.2f*v;
                p += v * atts[chb + i];
            }
            p += __shfl_down_sync(0xffffffffu, p, 4, 8);
            p += __shfl_down_sync(0xffffffffu, p, 2, 8);
            p += __shfl_down_sync(0xffffffffu, p, 1, 8);
            if ((lane & 7) == 0) ea[e*4 + h4] = p;
        }
    }
    __syncthreads();

    for (int it = tid; it < 1080; it += 256){
        int e = it >> 2, h = it & 3;
        atomicMax(&emaxu[dsts[e]*4 + h], ford(ea[it]));
    }
    __syncthreads();
    for (int it = tid; it < 1080; it += 256){
        int e = it >> 2, h = it & 3; int d = dsts[e];
        float ex = __expf(ea[it] - finv(emaxu[d*4 + h]));
        ea[it] = ex;
        atomicAdd(&esum[d*4 + h], ex);
    }
    __syncthreads();
    for (int it = tid; it < 1080; it += 256){
        int e = it >> 2, h = it & 3;
        float a = ea[it] / esum[dsts[e]*4 + h];
        ea[it] = a;
        if (alphaOut){
            int grow = (e < EPG) ? (b*EPG + e) : (NEDGE + b*NN + (e - EPG));
            alphaOut[(size_t)grow*4 + h] = a;
        }
    }
    for (int e = tid; e < 270; e += 256){
        int d = dsts[e];
        int slot = atomicAdd(&cnt[d], 1);
        if (slot < 48) lists[d*48 + slot] = e;
    }
    __syncthreads();

    {
        const int c = tid, hh = c >> 6;
        float bv = bias[c];
        for (int n = 0; n < NN; n++){
            float a = 0.f;
            int deg = cnt[n]; if (deg > 48) deg = 48;
            for (int i = 0; i < deg; i++){
                int e = lists[n*48 + i];
                a += ea[e*4 + hh] * xl[srcs[e]*256 + c];
            }
            float v = a + bv;
            g_h[((size_t)(b*NN + n))*256 + c] = v > 0.f ? v : 0.f;
        }
    }
}

// ==================== TF32 mma TCN block, shuffle-LN epilogue ====================
// Per CTA (2 graphs): C[64 x COUT] = A[64 x 3*CIN] @ W[3*CIN x COUT], NCHUNK=128 col chunks.
// LN over rows done with shfl.xor butterflies on fragments; no C staging in smem.
// Conv bias cancels inside LN (constant along normalized axis) -> omitted.
template<int CIN, int COUT, int DIL, bool HAS_DS>
__device__ __forceinline__ void tcn_mma(
    const float* __restrict__ srcY, const float* __restrict__ Wt, const float* __restrict__ Wds,
    const float* __restrict__ dsb,
    const float* __restrict__ lnw, const float* __restrict__ lnb,
    const float* __restrict__ resSrc, float* __restrict__ dstY)
{
    const int R = 40;
    const int NCHUNK = 128;
    const int NT = 2;                  // 2 n8-tiles per warp (8 warps * 16 cols)
    const int KS = CIN/8;
    extern __shared__ float smem[];
    float* hsp = smem;                 // 2*CIN*R

    const int tid  = threadIdx.x;
    const int warp = tid >> 5, lane = tid & 31;
    const int g = lane >> 2, tig = lane & 3;
    const int b0g = blockIdx.x*2;

    for (int i = tid; i < 2*CIN*R; i += 256) hsp[i] = 0.f;
    __syncthreads();
    for (int idx = tid; idx < 2*30*CIN; idx += 256){
        int gg = idx / (30*CIN); int r = idx - gg*30*CIN;
        int l = r / CIN, c = r - l*CIN;
        hsp[(gg*CIN + c)*R + DIL + l] = tf32r(srcY[((size_t)((b0g+gg)*30) + l)*CIN + c]);
    }
    __syncthreads();

    // per-thread LN params for rows l = g + 8*idx
    float lnw4[4], lnb4[4];
    #pragma unroll
    for (int idx = 0; idx < 4; idx++){
        int l = g + 8*idx;
        lnw4[idx] = (l < 30) ? __ldg(&lnw[l]) : 0.f;
        lnb4[idx] = (l < 30) ? __ldg(&lnb[l]) : 0.f;
    }

    for (int chunk = 0; chunk < COUT/NCHUNK; chunk++){
        const int nbase = chunk*NCHUNK + warp*(NCHUNK/8);
        float acc[4][NT][4];
        float accd[HAS_DS?4:1][NT][4];
        #pragma unroll
        for (int mt=0; mt<4; mt++)
            #pragma unroll
            for (int nt=0; nt<NT; nt++)
                #pragma unroll
                for (int q=0; q<4; q++){
                    acc[mt][nt][q] = 0.f;
                    if (HAS_DS) accd[mt][nt][q] = 0.f;
                }

        #pragma unroll
        for (int t = 0; t < 3; t++){
            const float* Wk = Wt + (size_t)(t*CIN)*COUT + nbase;
            const int aoff = DIL*t;
            for (int kk = 0; kk < KS; kk++){
                unsigned A[4][4];
                #pragma unroll
                for (int mt=0; mt<4; mt++){
                    const float* base = &hsp[((mt>>1)*CIN + kk*8 + tig)*R + aoff + (mt&1)*16 + g];
                    A[mt][0] = __float_as_uint(base[0]);
                    A[mt][1] = __float_as_uint(base[8]);
                    A[mt][2] = __float_as_uint(base[4*R]);
                    A[mt][3] = __float_as_uint(base[4*R + 8]);
                }
                const float* Wrow = Wk + (size_t)kk*8*COUT;
                #pragma unroll
                for (int nt=0; nt<NT; nt++){
                    unsigned br0 = __float_as_uint(__ldg(&Wrow[tig*COUT + nt*8 + g]));
                    unsigned br1 = __float_as_uint(__ldg(&Wrow[(tig+4)*COUT + nt*8 + g]));
                    #pragma unroll
                    for (int mt=0; mt<4; mt++) mma8(acc[mt][nt], A[mt], br0, br1);
                }
            }
        }
        if (HAS_DS){
            const float* Wk = Wds + nbase;
            for (int kk = 0; kk < KS; kk++){
                unsigned A[4][4];
                #pragma unroll
                for (int mt=0; mt<4; mt++){
                    const float* base = &hsp[((mt>>1)*CIN + kk*8 + tig)*R + DIL + (mt&1)*16 + g];
                    A[mt][0] = __float_as_uint(base[0]);
                    A[mt][1] = __float_as_uint(base[8]);
                    A[mt][2] = __float_as_uint(base[4*R]);
                    A[mt][3] = __float_as_uint(base[4*R + 8]);
                }
                const float* Wrow = Wk + (size_t)kk*8*COUT;
                #pragma unroll
                for (int nt=0; nt<NT; nt++){
                    unsigned br0 = __float_as_uint(__ldg(&Wrow[tig*COUT + nt*8 + g]));
                    unsigned br1 = __float_as_uint(__ldg(&Wrow[(tig+4)*COUT + nt*8 + g]));
                    #pragma unroll
                    for (int mt=0; mt<4; mt++) mma8(accd[mt][nt], A[mt], br0, br1);
                }
            }
        }

        // ---- shuffle-LN epilogue (per warp, no smem, no syncs) ----
        #pragma unroll
        for (int gg = 0; gg < 2; gg++){
            #pragma unroll
            for (int nt = 0; nt < NT; nt++){
                const int colb = nbase + nt*8 + 2*tig;
                float sx = 0.f, sy = 0.f;
                #pragma unroll
                for (int p = 0; p < 2; p++)
                    #pragma unroll
                    for (int q = 0; q < 4; q++){
                        int idx = (q>>1) + 2*p;
                        bool valid = (idx < 3) || (g < 6);
                        if (valid){
                            float val = acc[2*gg+p][nt][q];
                            if (q & 1) sy += val; else sx += val;
                        }
                    }
                #pragma unroll
                for (int off = 4; off < 32; off <<= 1){
                    sx += __shfl_xor_sync(0xffffffffu, sx, off);
                    sy += __shfl_xor_sync(0xffffffffu, sy, off);
                }
                float mux = sx*(1.f/30.f), muy = sy*(1.f/30.f);
                float vx = 0.f, vy = 0.f;
                #pragma unroll
                for (int p = 0; p < 2; p++)
                    #pragma unroll
                    for (int q = 0; q < 4; q++){
                        int idx = (q>>1) + 2*p;
                        bool valid = (idx < 3) || (g < 6);
                        if (valid){
                            float val = acc[2*gg+p][nt][q];
                            if (q & 1){ float d = val - muy; vy += d*d; }
                            else      { float d = val - mux; vx += d*d; }
                        }
                    }
                #pragma unroll
                for (int off = 4; off < 32; off <<= 1){
                    vx += __shfl_xor_sync(0xffffffffu, vx, off);
                    vy += __shfl_xor_sync(0xffffffffu, vy, off);
                }
                float rsx = rsqrtf(vx*(1.f/30.f) + 1e-5f);
                float rsy = rsqrtf(vy*(1.f/30.f) + 1e-5f);
                float dbv0 = 0.f, dbv1 = 0.f;
                if (HAS_DS){ dbv0 = __ldg(&dsb[colb]); dbv1 = __ldg(&dsb[colb+1]); }
                #pragma unroll
                for (int p = 0; p < 2; p++)
                    #pragma unroll
                    for (int h = 0; h < 2; h++){
                        int idx = h + 2*p;
                        int l = g + 8*idx;
                        if (l < 30){
                            float o0 = (acc[2*gg+p][nt][2*h]   - mux)*rsx*lnw4[idx] + lnb4[idx];
                            float o1 = (acc[2*gg+p][nt][2*h+1] - muy)*rsy*lnw4[idx] + lnb4[idx];
                            o0 = o0 > 0.f ? o0 : 0.f;
                            o1 = o1 > 0.f ? o1 : 0.f;
                            float r0, r1;
                            if (HAS_DS){
                                r0 = accd[2*gg+p][nt][2*h]   + dbv0;
                                r1 = accd[2*gg+p][nt][2*h+1] + dbv1;
                            } else {
                                float2 rr = *(const float2*)&resSrc[((size_t)((b0g+gg)*30) + l)*COUT + colb];
                                r0 = rr.x; r1 = rr.y;
                            }
                            float2 o; o.x = o0 + r0; o.y = o1 + r1;
                            *(float2*)&dstY[((size_t)((b0g+gg)*30) + l)*COUT + colb] = o;
                        }
                    }
            }
        }
    }
}

__global__ __launch_bounds__(256,2) void k_tcn0m(const float* __restrict__ lnw, const float* __restrict__ lnb){
    tcn_mma<256,256,1,false>(g_h, g_w0t, nullptr, nullptr, lnw, lnb, g_h, g_y0);
}
__global__ __launch_bounds__(256,2) void k_tcn1m(const float* __restrict__ dsb,
    const float* __restrict__ lnw, const float* __restrict__ lnb){
    tcn_mma<256,512,2,true>(g_y0, g_w1t, g_ds1t, dsb, lnw, lnb, nullptr, g_y1);
}
__global__ __launch_bounds__(256) void k_tcn2m(const float* __restrict__ dsb,
    const float* __restrict__ lnw, const float* __restrict__ lnb){
    tcn_mma<512,256,4,true>(g_y1, g_w2t, g_ds2t, dsb, lnw, lnb, nullptr, g_y2);
}

// ---- tiled GEMM body (f32x2): C[M,N] = act(A[M,K] @ Bw[N,K]^T + bias) ----
__device__ __forceinline__ void gemm_body(const float* __restrict__ A, const float* __restrict__ Bw,
    const float* __restrict__ bias, float* __restrict__ C, int M, int N, int K, bool doRelu)
{
    __shared__ __align__(16) float As2[16][68];
    __shared__ __align__(16) float Bs2[16][68];
    const int tid = threadIdx.x;
    const int tx = tid & 15, ty = tid >> 4;
    const int m0 = blockIdx.y*64, n0 = blockIdx.x*64;
    const int lm = tid >> 2, lk = (tid & 3)*4;
    u64 acc2[4][2];
    #pragma unroll
    for (int i = 0; i < 4; i++){ acc2[i][0] = 0ull; acc2[i][1] = 0ull; }

    for (int k0 = 0; k0 < K; k0 += 16){
        float4 av = *(const float4*)&A[(size_t)(m0+lm)*K + k0 + lk];
        float4 bv = make_float4(0.f,0.f,0.f,0.f);
        if (n0 + lm < N) bv = *(const float4*)&Bw[(size_t)(n0+lm)*K + k0 + lk];
        As2[lk+0][lm] = av.x; As2[lk+1][lm] = av.y; As2[lk+2][lm] = av.z; As2[lk+3][lm] = av.w;
        Bs2[lk+0][lm] = bv.x; Bs2[lk+1][lm] = bv.y; Bs2[lk+2][lm] = bv.z; Bs2[lk+3][lm] = bv.w;
        __syncthreads();
        #pragma unroll
        for (int k = 0; k < 16; k++){
            float4 a = *(const float4*)&As2[k][ty*4];
            u64 bp0 = *(const u64*)&Bs2[k][tx*4];
            u64 bp1 = *(const u64*)&Bs2[k][tx*4+2];
            u64 a0 = dup2(a.x), a1 = dup2(a.y), a2 = dup2(a.z), a3 = dup2(a.w);
            fma2(acc2[0][0], a0, bp0); fma2(acc2[0][1], a0, bp1);
            fma2(acc2[1][0], a1, bp0); fma2(acc2[1][1], a1, bp1);
            fma2(acc2[2][0], a2, bp0); fma2(acc2[2][1], a2, bp1);
            fma2(acc2[3][0], a3, bp0); fma2(acc2[3][1], a3, bp1);
        }
        __syncthreads();
    }
    #pragma unroll
    for (int i = 0; i < 4; i++){
        int row = m0 + ty*4 + i;
        float2 p0 = unp2(acc2[i][0]), p1 = unp2(acc2[i][1]);
        float vals[4] = {p0.x, p0.y, p1.x, p1.y};
        #pragma unroll
        for (int j = 0; j < 4; j++){
            int col = n0 + tx*4 + j;
            if (col < N){
                float v = vals[j] + __ldg(&bias[col]);
                if (doRelu) v = v > 0.f ? v : 0.f;
                C[(size_t)row*N + col] = v;
            }
        }
    }
}
__global__ __launch_bounds__(256) void k_fc1(const float* __restrict__ bias){
    gemm_body(g_y2, g_fc1p, bias, g_z1, 1024, 512, 7680, true);
}
__global__ __launch_bounds__(256) void k_fc2(const float* __restrict__ w, const float* __restrict__ bias){
    gemm_body(g_z1, w, bias, g_z2, 1024, 256, 512, true);
}
__global__ __launch_bounds__(256) void k_fc3(const float* __restrict__ w, const float* __restrict__ bias,
                                             float* __restrict__ out){
    gemm_body(g_z2, w, bias, out, 1024, 144, 256, false);
}

extern "C" void kernel_launch(void* const* d_in, const int* in_sizes, int n_in,
                              void* d_out, int out_size) {
    const float* x      = (const float*)d_in[0];
    const float* gWl    = (const float*)d_in[1];
    const float* gbl    = (const float*)d_in[2];
    const float* gWr    = (const float*)d_in[3];
    const float* gbr    = (const float*)d_in[4];
    const float* gatt   = (const float*)d_in[5];
    const float* gbias  = (const float*)d_in[6];
    const float* t0w    = (const float*)d_in[7];
    const float* ln0w   = (const float*)d_in[9];
    const float* ln0b   = (const float*)d_in[10];
    const float* t1w    = (const float*)d_in[11];
    const float* ln1w   = (const float*)d_in[13];
    const float* ln1b   = (const float*)d_in[14];
    const float* ds1w   = (const float*)d_in[15];
    const float* ds1b   = (const float*)d_in[16];
    const float* t2w    = (const float*)d_in[17];
    const float* ln2w   = (const float*)d_in[19];
    const float* ln2b   = (const float*)d_in[20];
    const float* ds2w   = (const float*)d_in[21];
    const float* ds2b   = (const float*)d_in[22];
    const float* fc1w   = (const float*)d_in[23];
    const float* fc1b   = (const float*)d_in[24];
    const float* fc2w   = (const float*)d_in[25];
    const float* fc2b   = (const float*)d_in[26];
    const float* fc3w   = (const float*)d_in[27];
    const float* fc3b   = (const float*)d_in[28];
    const int*   eidx   = (const int*)d_in[29];

    float* outp = (float*)d_out;
    bool full = (out_size >= 147456 + ETOT*4 + 2*ETOT);
    float* alphaOut = full ? (outp + 147456) : nullptr;
    float* eiOut    = full ? (outp + 147456 + ETOT*4) : nullptr;

    const int SM0 = 2*256*40*4;   // 81,920
    const int SM1 = 2*256*40*4;   // 81,920
    const int SM2 = 2*512*40*4;   // 163,840

    cudaFuncSetAttribute(k_gat,   cudaFuncAttributeMaxDynamicSharedMemorySize, 84*1024);
    cudaFuncSetAttribute(k_tcn0m, cudaFuncAttributeMaxDynamicSharedMemorySize, SM0);
    cudaFuncSetAttribute(k_tcn1m, cudaFuncAttributeMaxDynamicSharedMemorySize, SM1);
    cudaFuncSetAttribute(k_tcn2m, cudaFuncAttributeMaxDynamicSharedMemorySize, SM2);

    k_tr_wlr<<<64,256>>>(gWl, gWr);
    k_tr_w0 <<<768,256>>>(t0w);
    k_tr_w1 <<<1536,256>>>(t1w);
    k_tr_ds1<<<512,256>>>(ds1w);
    k_tr_w2 <<<1536,256>>>(t2w);
    k_tr_ds2<<<512,256>>>(ds2w);
    k_tr_fc1<<<15360,256>>>(fc1w);
    if (eiOut) k_ei<<<1080,256>>>(eidx, eiOut);

    k_gat<<<1024,256, 84*1024>>>(x, gbl, gbr, gatt, gbias, eidx, alphaOut);
    k_tcn0m<<<512,256, SM0>>>(ln0w, ln0b);
    k_tcn1m<<<512,256, SM1>>>(ds1b, ln1w, ln1b);
    k_tcn2m<<<512,256, SM2>>>(ds2b, ln2w, ln2b);

    dim3 g1(8,16);  k_fc1<<<g1,256>>>(fc1b);
    dim3 g2(4,16);  k_fc2<<<g2,256>>>(fc2w, fc2b);
    dim3 g3(3,16);  k_fc3<<<g3,256>>>(fc3w, fc3b, outp);
}